// round 2
// baseline (speedup 1.0000x reference)
#include <cuda_runtime.h>
#include <math.h>

#define NB 8
#define NL 12
#define NS 1023
#define NS1 1024
#define NE 768
#define NH 12
#define ND 64
#define NV 50257
#define NFF 3072
#define NE3 2304

// ---------------- scratch (device globals: no allocation allowed) -------------
__device__ __align__(16) float g_states[NB*NE];
__device__ __align__(16) float g_xln[NB*NE];
__device__ __align__(16) float g_qkv[NB*NE3];
__device__ __align__(16) float g_ctx[NB*NE];
__device__ __align__(16) float g_hbuf[NB*NFF];
__device__ __align__(16) float g_scores[NB*NH*NS1];
__device__ __align__(16) float g_logits[NB*NV];
__device__ int g_lp[NB];

// ---------------- embedding + last-position -----------------------------------
__global__ void embed_kernel(const int* __restrict__ ids, const int* __restrict__ mask,
                             const float* __restrict__ wte, const float* __restrict__ wpe){
    int b = blockIdx.x, tid = threadIdx.x;
    __shared__ int s_lp;
    if (tid < 32){
        int best = -1;
        for (int s = tid; s < NS1; s += 32)
            if (mask[b*NS1 + s] != 0) best = (s > best) ? s : best;
        for (int o = 16; o; o >>= 1){
            int ot = __shfl_xor_sync(0xffffffffu, best, o);
            best = (ot > best) ? ot : best;
        }
        if (tid == 0){ s_lp = best; g_lp[b] = best; }
    }
    __syncthreads();
    int lp  = s_lp;
    int tok = ids[b*NS1 + lp];
    for (int e = tid; e < NE; e += blockDim.x)
        g_states[b*NE + e] = wte[(size_t)tok*NE + e] + wpe[(size_t)lp*NE + e];
}

// ---------------- layernorm + scratch zeroing ----------------------------------
__global__ void ln_prep_kernel(const float* __restrict__ src, const float* __restrict__ w,
                               const float* __restrict__ bb, float* __restrict__ out,
                               float* z1, int n1, float* z2, int n2){
    int b = blockIdx.x, tid = threadIdx.x;
    __shared__ float red[256];
    const float* x = src + b*NE;
    float s = 0.f;
    for (int i = tid; i < NE; i += 256) s += x[i];
    red[tid] = s; __syncthreads();
    for (int o = 128; o; o >>= 1){ if (tid < o) red[tid] += red[tid+o]; __syncthreads(); }
    float mean = red[0] * (1.0f/NE);
    __syncthreads();
    float v = 0.f;
    for (int i = tid; i < NE; i += 256){ float d = x[i]-mean; v += d*d; }
    red[tid] = v; __syncthreads();
    for (int o = 128; o; o >>= 1){ if (tid < o) red[tid] += red[tid+o]; __syncthreads(); }
    float rs = rsqrtf(red[0]*(1.0f/NE) + 1e-5f);
    for (int i = tid; i < NE; i += 256)
        out[b*NE + i] = (x[i]-mean)*rs*w[i] + bb[i];
    int g = b*256 + tid;
    if (z1) for (int i = g; i < n1; i += 2048) z1[i] = 0.f;
    if (z2) for (int i = g; i < n2; i += 2048) z2[i] = 0.f;
}

// ---------------- batched GEMV: out[b,j] (+)= sum_e x[b,e]*W[e,j] (+ bias) -----
// grid (jBlocks, eChunks); e-chunk blocks accumulate via atomics; chunk 0 adds bias.
__global__ void gemv_kernel(const float* __restrict__ x, const float* __restrict__ W,
                            const float* __restrict__ bias, float* __restrict__ out,
                            int M, int N, int CH, int dogelu){
    __shared__ __align__(16) float xs[8*32];
    int tid = threadIdx.x;
    int e0 = blockIdx.y * CH;
    int ec = M - e0; if (ec > CH) ec = CH;
    for (int i = tid; i < 8*ec; i += blockDim.x){
        int b2 = i / ec, e = i - b2*ec;
        float v = x[b2*M + e0 + e];
        if (dogelu) v = 0.5f*v*(1.0f + erff(v*0.70710678118654752f));
        xs[b2*32 + e] = v;
    }
    __syncthreads();
    int j = (blockIdx.x*blockDim.x + tid)*4;
    if (j >= N) return;
    float4 acc[8];
    #pragma unroll
    for (int b2 = 0; b2 < 8; b2++) acc[b2] = make_float4(0.f,0.f,0.f,0.f);
    const float* Wp = W + (size_t)e0*N + j;
    for (int e = 0; e < ec; e++){
        float4 w4 = *(const float4*)Wp; Wp += N;
        #pragma unroll
        for (int b2 = 0; b2 < 8; b2++){
            float xv = xs[b2*32 + e];
            acc[b2].x = fmaf(xv, w4.x, acc[b2].x);
            acc[b2].y = fmaf(xv, w4.y, acc[b2].y);
            acc[b2].z = fmaf(xv, w4.z, acc[b2].z);
            acc[b2].w = fmaf(xv, w4.w, acc[b2].w);
        }
    }
    if (blockIdx.y == 0){
        float4 bv = *(const float4*)(bias + j);
        #pragma unroll
        for (int b2 = 0; b2 < 8; b2++){
            acc[b2].x += bv.x; acc[b2].y += bv.y; acc[b2].z += bv.z; acc[b2].w += bv.w;
        }
    }
    #pragma unroll
    for (int b2 = 0; b2 < 8; b2++){
        float* p = out + (size_t)b2*N + j;
        atomicAdd(p+0, acc[b2].x); atomicAdd(p+1, acc[b2].y);
        atomicAdd(p+2, acc[b2].z); atomicAdd(p+3, acc[b2].w);
    }
}

// ---------------- attention scores + K copy into new_kv ------------------------
// grid (B, 16) x 256 thr: block handles 64 seq rows; warp handles a row at a time.
__global__ void attn_score_kernel(const float* __restrict__ kv, const float* __restrict__ abias,
                                  const int* __restrict__ mask, float* __restrict__ nkv, int l){
    int b = blockIdx.x, sc = blockIdx.y;
    int tid = threadIdx.x, warp = tid >> 5, lane = tid & 31;
    __shared__ __align__(16) float qs[NE];
    for (int i = tid; i < NE; i += 256) qs[i] = g_qkv[b*NE3 + i];
    __syncthreads();
    int lp = g_lp[b];
    const float* kc = kv  + ((size_t)(l*2+0)*NB + b)*(size_t)NS *NE;
    float*       ko = nkv ? nkv + ((size_t)(l*2+0)*NB + b)*(size_t)NS1*NE : nullptr;
    for (int it = 0; it < 8; it++){
        int s = sc*64 + it*8 + warp;
        const float* src = nullptr;
        if (s == lp)      src = g_qkv + b*NE3 + NE;            // new K row
        else if (s != NS) src = kc + (size_t)s*NE;             // cache row (s==NS && lp!=NS -> zeros)
        float part[6];
        #pragma unroll
        for (int c = 0; c < 6; c++){
            int e = c*128 + lane*4;
            float4 v4 = src ? *(const float4*)(src + e) : make_float4(0.f,0.f,0.f,0.f);
            if (ko) *(float4*)(ko + (size_t)s*NE + e) = v4;
            part[c] = v4.x*qs[e] + v4.y*qs[e+1] + v4.z*qs[e+2] + v4.w*qs[e+3];
        }
        #pragma unroll
        for (int c = 0; c < 6; c++){
            float p = part[c];
            p += __shfl_xor_sync(0xffffffffu, p, 8);
            p += __shfl_xor_sync(0xffffffffu, p, 4);
            p += __shfl_xor_sync(0xffffffffu, p, 2);
            p += __shfl_xor_sync(0xffffffffu, p, 1);
            part[c] = p;
        }
        if ((lane & 15) == 0){
            int hb = lane >> 4;                 // 0 or 1
            bool msk = (mask[b*NS1 + s] == 0);
            float ab = abias[s];
            #pragma unroll
            for (int c = 0; c < 6; c++){
                int h = 2*c + hb;
                g_scores[(b*NH + h)*NS1 + s] = msk ? -1e9f : (part[c]*0.125f + ab);
            }
        }
    }
}

// ---------------- softmax over seq per (b,h), in place -------------------------
__global__ void softmax_kernel(){
    int bh = blockIdx.x, tid = threadIdx.x;
    float* row = g_scores + (size_t)bh*NS1;
    __shared__ float red[256];
    float v[4]; float m = -1e30f;
    #pragma unroll
    for (int k = 0; k < 4; k++){ v[k] = row[tid + k*256]; m = fmaxf(m, v[k]); }
    red[tid] = m; __syncthreads();
    for (int o = 128; o; o >>= 1){ if (tid < o) red[tid] = fmaxf(red[tid], red[tid+o]); __syncthreads(); }
    m = red[0]; __syncthreads();
    float s = 0.f;
    #pragma unroll
    for (int k = 0; k < 4; k++){ v[k] = expf(v[k]-m); s += v[k]; }
    red[tid] = s; __syncthreads();
    for (int o = 128; o; o >>= 1){ if (tid < o) red[tid] += red[tid+o]; __syncthreads(); }
    float inv = 1.0f/red[0];
    #pragma unroll
    for (int k = 0; k < 4; k++) row[tid + k*256] = v[k]*inv;
}

// ---------------- weighted-V accumulation + V copy into new_kv -----------------
// grid (B, 16) x 192 thr: thread owns 4 head-dims across 64 rows; atomic ctx add.
__global__ void attn_v_kernel(const float* __restrict__ kv, float* __restrict__ nkv, int l){
    int b = blockIdx.x, sc = blockIdx.y, tid = threadIdx.x;
    int e = tid*4, h = tid >> 4;
    __shared__ __align__(16) float ws[NH*64];
    for (int i = tid; i < NH*64; i += 192){
        int hh = i >> 6, si = i & 63;
        ws[i] = g_scores[(b*NH + hh)*NS1 + sc*64 + si];
    }
    __syncthreads();
    int lp = g_lp[b];
    const float* vc = kv  + ((size_t)(l*2+1)*NB + b)*(size_t)NS *NE;
    float*       vo = nkv ? nkv + ((size_t)(l*2+1)*NB + b)*(size_t)NS1*NE : nullptr;
    float4 acc = make_float4(0.f,0.f,0.f,0.f);
    for (int i = 0; i < 64; i++){
        int s = sc*64 + i;
        float w = ws[h*64 + i];
        float4 v4;
        if (s == lp)      v4 = *(const float4*)(g_qkv + b*NE3 + 2*NE + e);
        else if (s == NS) v4 = make_float4(0.f,0.f,0.f,0.f);
        else              v4 = *(const float4*)(vc + (size_t)s*NE + e);
        if (vo) *(float4*)(vo + (size_t)s*NE + e) = v4;
        acc.x = fmaf(w, v4.x, acc.x); acc.y = fmaf(w, v4.y, acc.y);
        acc.z = fmaf(w, v4.z, acc.z); acc.w = fmaf(w, v4.w, acc.w);
    }
    float* p = g_ctx + b*NE + e;
    atomicAdd(p+0, acc.x); atomicAdd(p+1, acc.y);
    atomicAdd(p+2, acc.z); atomicAdd(p+3, acc.w);
}

// ---------------- lm head: logits[b,t] = ln_f(states)[b] . wte[t] ---------------
// 128 thr/block, 2 vocab rows per thread (register-tiled over 8 batches).
__global__ void lm_kernel(const float* __restrict__ wte){
    __shared__ __align__(16) float xs[NB*NE];
    int tid = threadIdx.x;
    for (int i = tid; i < NB*NE; i += 128) xs[i] = g_xln[i];
    __syncthreads();
    long long t0 = ((long long)blockIdx.x*128 + tid)*2;
    if (t0 >= NV) return;
    long long t1 = (t0+1 < NV) ? t0+1 : t0;
    const float* r0 = wte + (size_t)t0*NE;
    const float* r1 = wte + (size_t)t1*NE;
    float acc[16];
    #pragma unroll
    for (int i = 0; i < 16; i++) acc[i] = 0.f;
    for (int e = 0; e < NE; e += 4){
        float4 w0 = *(const float4*)(r0 + e);
        float4 w1 = *(const float4*)(r1 + e);
        #pragma unroll
        for (int b2 = 0; b2 < 8; b2++){
            float4 x4 = *(const float4*)&xs[b2*NE + e];
            acc[b2]   = fmaf(w0.x,x4.x, fmaf(w0.y,x4.y, fmaf(w0.z,x4.z, fmaf(w0.w,x4.w, acc[b2]))));
            acc[8+b2] = fmaf(w1.x,x4.x, fmaf(w1.y,x4.y, fmaf(w1.z,x4.z, fmaf(w1.w,x4.w, acc[8+b2]))));
        }
    }
    #pragma unroll
    for (int b2 = 0; b2 < 8; b2++){
        g_logits[(size_t)b2*NV + t0] = acc[b2];
        if (t0+1 < NV) g_logits[(size_t)b2*NV + t0+1] = acc[8+b2];
    }
}

// ---------------- vocab softmax + argmax ---------------------------------------
__global__ void finish_kernel(float* __restrict__ probs, float* __restrict__ chosen_f,
                              int* __restrict__ chosen_i){
    int b = blockIdx.x, tid = threadIdx.x;
    __shared__ float rv[1024];
    __shared__ int   ri[1024];
    const float* lg = g_logits + (size_t)b*NV;
    float m = -1e30f; int mi = 0;
    for (int t = tid; t < NV; t += 1024){
        float v = lg[t];
        if (v > m){ m = v; mi = t; }
    }
    rv[tid] = m; ri[tid] = mi; __syncthreads();
    for (int o = 512; o; o >>= 1){
        if (tid < o){
            if (rv[tid+o] > rv[tid] || (rv[tid+o] == rv[tid] && ri[tid+o] < ri[tid])){
                rv[tid] = rv[tid+o]; ri[tid] = ri[tid+o];
            }
        }
        __syncthreads();
    }
    float mx = rv[0]; int am = ri[0]; __syncthreads();
    float s = 0.f;
    for (int t = tid; t < NV; t += 1024) s += expf(lg[t]-mx);
    rv[tid] = s; __syncthreads();
    for (int o = 512; o; o >>= 1){ if (tid < o) rv[tid] += rv[tid+o]; __syncthreads(); }
    float inv = 1.0f/rv[0];
    if (probs)
        for (int t = tid; t < NV; t += 1024)
            probs[(size_t)b*NV + t] = expf(lg[t]-mx)*inv;
    if (tid == 0){
        if (chosen_f) chosen_f[b] = (float)am;
        if (chosen_i) chosen_i[b] = am;
    }
}

// ---------------- launch --------------------------------------------------------
extern "C" void kernel_launch(void* const* d_in, const int* in_sizes, int n_in,
                              void* d_out, int out_size){
    const int*   ids  = (const int*)  d_in[0];
    const int*   mask = (const int*)  d_in[1];
    const float* kv   = (const float*)d_in[2];
    const float* wte  = (const float*)d_in[3];
    const float* wpe  = (const float*)d_in[4];
    const float* ln1w = (const float*)d_in[5];
    const float* ln1b = (const float*)d_in[6];
    const float* caw  = (const float*)d_in[7];
    const float* cab  = (const float*)d_in[8];
    const float* ab   = (const float*)d_in[9];
    const float* cpw  = (const float*)d_in[10];
    const float* cpb  = (const float*)d_in[11];
    const float* ln2w = (const float*)d_in[12];
    const float* ln2b = (const float*)d_in[13];
    const float* fcw  = (const float*)d_in[14];
    const float* fcb  = (const float*)d_in[15];
    const float* prw  = (const float*)d_in[16];
    const float* prb  = (const float*)d_in[17];
    const float* lnfw = (const float*)d_in[18];
    const float* lnfb = (const float*)d_in[19];

    float *st, *xln, *qkvp, *ctxp, *hb;
    cudaGetSymbolAddress((void**)&st,   g_states);
    cudaGetSymbolAddress((void**)&xln,  g_xln);
    cudaGetSymbolAddress((void**)&qkvp, g_qkv);
    cudaGetSymbolAddress((void**)&ctxp, g_ctx);
    cudaGetSymbolAddress((void**)&hb,   g_hbuf);

    long long nkvN  = (long long)NL*2*NB*NS1*NE;                  // 150,994,944
    long long fullN = (long long)NB + (long long)NB*NV + nkvN;    // 151,397,008
    float* outf = (float*)d_out;
    float* chosen_f = nullptr; int* chosen_i = nullptr;
    float* probs = nullptr; float* nkv = nullptr;
    long long osz = (long long)out_size;
    if (osz == fullN){ chosen_f = outf; probs = outf + NB; nkv = outf + NB + (long long)NB*NV; }
    else if (osz == nkvN){ nkv = outf; }
    else if (osz == (long long)NB*NV){ probs = outf; }
    else if (osz == (long long)NB){ chosen_i = (int*)d_out; }
    else if (osz == (long long)NB + (long long)NB*NV){ chosen_f = outf; probs = outf + NB; }
    else {
        chosen_f = outf;
        if (osz >= (long long)NB + (long long)NB*NV) probs = outf + NB;
        if (osz >= fullN) nkv = outf + NB + (long long)NB*NV;
    }

    embed_kernel<<<NB,256>>>(ids, mask, wte, wpe);
    for (int l = 0; l < NL; l++){
        ln_prep_kernel<<<NB,256>>>(st, ln1w + l*NE, ln1b + l*NE, xln, qkvp, NB*NE3, ctxp, NB*NE);
        gemv_kernel<<<dim3(3,48),256>>>(xln, caw + (size_t)l*NE*NE3, cab + (size_t)l*NE3,
                                        qkvp, NE, NE3, 16, 0);
        attn_score_kernel<<<dim3(NB,16),256>>>(kv, ab + (size_t)l*NS1, mask, nkv, l);
        softmax_kernel<<<NB*NH,256>>>();
        attn_v_kernel<<<dim3(NB,16),192>>>(kv, nkv, l);
        gemv_kernel<<<dim3(1,48),256>>>(ctxp, cpw + (size_t)l*NE*NE, cpb + (size_t)l*NE,
                                        st, NE, NE, 16, 0);
        ln_prep_kernel<<<NB,256>>>(st, ln2w + l*NE, ln2b + l*NE, xln, hb, NB*NFF, nullptr, 0);
        gemv_kernel<<<dim3(3,48),256>>>(xln, fcw + (size_t)l*NE*NFF, fcb + (size_t)l*NFF,
                                        hb, NE, NFF, 16, 0);
        gemv_kernel<<<dim3(1,128),256>>>(hb, prw + (size_t)l*NFF*NE, prb + (size_t)l*NE,
                                         st, NFF, NE, 24, 1);
    }
    ln_prep_kernel<<<NB,256>>>(st, lnfw, lnfb, xln, nullptr, 0, nullptr, 0);
    lm_kernel<<<(NV + 255)/256, 128>>>(wte);
    finish_kernel<<<NB,1024>>>(probs, chosen_f, chosen_i);
}

// round 3
// speedup vs baseline: 1.2990x; 1.2990x over previous
#include <cuda_runtime.h>
#include <math.h>

#define NB 8
#define NL 12
#define NS 1023
#define NS1 1024
#define NE 768
#define NH 12
#define ND 64
#define NV 50257
#define NFF 3072
#define NE3 2304

// ---------------- scratch (device globals: no allocation allowed) -------------
__device__ __align__(16) float g_states[NB*NE];
__device__ __align__(16) float g_xln[NB*NE];
__device__ __align__(16) float g_qkv[NB*NE3];
__device__ __align__(16) float g_ctx[NB*NE];
__device__ __align__(16) float g_hbuf[NB*NFF];
__device__ __align__(16) float g_scores[NB*NH*NS1];
__device__ __align__(16) float g_logits[NB*NV];
__device__ int g_lp[NB];

// ---------------- embedding + last-position -----------------------------------
__global__ void embed_kernel(const int* __restrict__ ids, const int* __restrict__ mask,
                             const float* __restrict__ wte, const float* __restrict__ wpe){
    int b = blockIdx.x, tid = threadIdx.x;
    __shared__ int s_lp;
    if (tid < 32){
        int best = -1;
        for (int s = tid; s < NS1; s += 32)
            if (mask[b*NS1 + s] != 0) best = (s > best) ? s : best;
        for (int o = 16; o; o >>= 1){
            int ot = __shfl_xor_sync(0xffffffffu, best, o);
            best = (ot > best) ? ot : best;
        }
        if (tid == 0){ s_lp = best; g_lp[b] = best; }
    }
    __syncthreads();
    int lp  = s_lp;
    int tok = ids[b*NS1 + lp];
    for (int e = tid; e < NE; e += blockDim.x)
        g_states[b*NE + e] = wte[(size_t)tok*NE + e] + wpe[(size_t)lp*NE + e];
}

// ---------------- layernorm + scratch zeroing ----------------------------------
__global__ void ln_prep_kernel(const float* __restrict__ src, const float* __restrict__ w,
                               const float* __restrict__ bb, float* __restrict__ out,
                               float* z1, int n1, float* z2, int n2){
    int b = blockIdx.x, tid = threadIdx.x;
    __shared__ float red[256];
    const float* x = src + b*NE;
    float s = 0.f;
    for (int i = tid; i < NE; i += 256) s += x[i];
    red[tid] = s; __syncthreads();
    for (int o = 128; o; o >>= 1){ if (tid < o) red[tid] += red[tid+o]; __syncthreads(); }
    float mean = red[0] * (1.0f/NE);
    __syncthreads();
    float v = 0.f;
    for (int i = tid; i < NE; i += 256){ float d = x[i]-mean; v += d*d; }
    red[tid] = v; __syncthreads();
    for (int o = 128; o; o >>= 1){ if (tid < o) red[tid] += red[tid+o]; __syncthreads(); }
    float rs = rsqrtf(red[0]*(1.0f/NE) + 1e-5f);
    for (int i = tid; i < NE; i += 256)
        out[b*NE + i] = (x[i]-mean)*rs*w[i] + bb[i];
    int g = b*256 + tid;
    if (z1) for (int i = g; i < n1; i += 2048) z1[i] = 0.f;
    if (z2) for (int i = g; i < n2; i += 2048) z2[i] = 0.f;
}

// ---------------- batched GEMV: out[b,j] (+)= sum_e x[b,e]*W[e,j] (+ bias) -----
__global__ void gemv_kernel(const float* __restrict__ x, const float* __restrict__ W,
                            const float* __restrict__ bias, float* __restrict__ out,
                            int M, int N, int CH, int dogelu){
    __shared__ __align__(16) float xs[8*32];
    int tid = threadIdx.x;
    int e0 = blockIdx.y * CH;
    int ec = M - e0; if (ec > CH) ec = CH;
    for (int i = tid; i < 8*ec; i += blockDim.x){
        int b2 = i / ec, e = i - b2*ec;
        float v = x[b2*M + e0 + e];
        if (dogelu) v = 0.5f*v*(1.0f + erff(v*0.70710678118654752f));
        xs[b2*32 + e] = v;
    }
    __syncthreads();
    int j = (blockIdx.x*blockDim.x + tid)*4;
    if (j >= N) return;
    float4 acc[8];
    #pragma unroll
    for (int b2 = 0; b2 < 8; b2++) acc[b2] = make_float4(0.f,0.f,0.f,0.f);
    const float* Wp = W + (size_t)e0*N + j;
    for (int e = 0; e < ec; e++){
        float4 w4 = *(const float4*)Wp; Wp += N;
        #pragma unroll
        for (int b2 = 0; b2 < 8; b2++){
            float xv = xs[b2*32 + e];
            acc[b2].x = fmaf(xv, w4.x, acc[b2].x);
            acc[b2].y = fmaf(xv, w4.y, acc[b2].y);
            acc[b2].z = fmaf(xv, w4.z, acc[b2].z);
            acc[b2].w = fmaf(xv, w4.w, acc[b2].w);
        }
    }
    if (blockIdx.y == 0){
        float4 bv = *(const float4*)(bias + j);
        #pragma unroll
        for (int b2 = 0; b2 < 8; b2++){
            acc[b2].x += bv.x; acc[b2].y += bv.y; acc[b2].z += bv.z; acc[b2].w += bv.w;
        }
    }
    #pragma unroll
    for (int b2 = 0; b2 < 8; b2++){
        float* p = out + (size_t)b2*N + j;
        atomicAdd(p+0, acc[b2].x); atomicAdd(p+1, acc[b2].y);
        atomicAdd(p+2, acc[b2].z); atomicAdd(p+3, acc[b2].w);
    }
}

// ---------------- attention scores + K copy into new_kv ------------------------
// grid (B, 128) x 256 thr: warp per seq row (8 rows per block).
__global__ void attn_score_kernel(const float* __restrict__ kv, const float* __restrict__ abias,
                                  const int* __restrict__ mask, float* __restrict__ nkv, int l){
    int b = blockIdx.x, sc = blockIdx.y;
    int tid = threadIdx.x, warp = tid >> 5, lane = tid & 31;
    __shared__ __align__(16) float qs[NE];
    for (int i = tid; i < NE; i += 256) qs[i] = g_qkv[b*NE3 + i];
    __syncthreads();
    int lp = g_lp[b];
    const float* kc = kv  + ((size_t)(l*2+0)*NB + b)*(size_t)NS *NE;
    float*       ko = nkv ? nkv + ((size_t)(l*2+0)*NB + b)*(size_t)NS1*NE : nullptr;
    int s = sc*8 + warp;
    const float* src = nullptr;
    if (s == lp)      src = g_qkv + b*NE3 + NE;            // new K row
    else if (s != NS) src = kc + (size_t)s*NE;             // cache row
    float4 v4[6];
    #pragma unroll
    for (int c = 0; c < 6; c++){
        int e = c*128 + lane*4;
        v4[c] = src ? *(const float4*)(src + e) : make_float4(0.f,0.f,0.f,0.f);
    }
    if (ko){
        #pragma unroll
        for (int c = 0; c < 6; c++)
            *(float4*)(ko + (size_t)s*NE + c*128 + lane*4) = v4[c];
    }
    float part[6];
    #pragma unroll
    for (int c = 0; c < 6; c++){
        int e = c*128 + lane*4;
        part[c] = v4[c].x*qs[e] + v4[c].y*qs[e+1] + v4[c].z*qs[e+2] + v4[c].w*qs[e+3];
    }
    #pragma unroll
    for (int c = 0; c < 6; c++){
        float p = part[c];
        p += __shfl_xor_sync(0xffffffffu, p, 8);
        p += __shfl_xor_sync(0xffffffffu, p, 4);
        p += __shfl_xor_sync(0xffffffffu, p, 2);
        p += __shfl_xor_sync(0xffffffffu, p, 1);
        part[c] = p;
    }
    if ((lane & 15) == 0){
        int hb = lane >> 4;                 // 0 or 1
        bool msk = (mask[b*NS1 + s] == 0);
        float ab = abias[s];
        #pragma unroll
        for (int c = 0; c < 6; c++){
            int h = 2*c + hb;
            g_scores[(b*NH + h)*NS1 + s] = msk ? -1e9f : (part[c]*0.125f + ab);
        }
    }
}

// ---------------- softmax over seq per (b,h), in place -------------------------
__global__ void softmax_kernel(){
    int bh = blockIdx.x, tid = threadIdx.x;
    float* row = g_scores + (size_t)bh*NS1;
    __shared__ float red[256];
    float v[4]; float m = -1e30f;
    #pragma unroll
    for (int k = 0; k < 4; k++){ v[k] = row[tid + k*256]; m = fmaxf(m, v[k]); }
    red[tid] = m; __syncthreads();
    for (int o = 128; o; o >>= 1){ if (tid < o) red[tid] = fmaxf(red[tid], red[tid+o]); __syncthreads(); }
    m = red[0]; __syncthreads();
    float s = 0.f;
    #pragma unroll
    for (int k = 0; k < 4; k++){ v[k] = expf(v[k]-m); s += v[k]; }
    red[tid] = s; __syncthreads();
    for (int o = 128; o; o >>= 1){ if (tid < o) red[tid] += red[tid+o]; __syncthreads(); }
    float inv = 1.0f/red[0];
    #pragma unroll
    for (int k = 0; k < 4; k++) row[tid + k*256] = v[k]*inv;
}

// ---------------- weighted-V accumulation + V copy into new_kv -----------------
// grid (B, 64) x 192 thr: block handles 16 seq rows; thread owns 4 head-dims.
__global__ void attn_v_kernel(const float* __restrict__ kv, float* __restrict__ nkv, int l){
    int b = blockIdx.x, sc = blockIdx.y, tid = threadIdx.x;
    int e = tid*4, h = tid >> 4;
    __shared__ __align__(16) float ws[NH*16];
    {
        int hh = tid >> 4, si = tid & 15;
        ws[tid] = g_scores[(b*NH + hh)*NS1 + sc*16 + si];
    }
    __syncthreads();
    int lp = g_lp[b];
    const float* vc = kv  + ((size_t)(l*2+1)*NB + b)*(size_t)NS *NE;
    float*       vo = nkv ? nkv + ((size_t)(l*2+1)*NB + b)*(size_t)NS1*NE : nullptr;
    float4 acc = make_float4(0.f,0.f,0.f,0.f);
    #pragma unroll 4
    for (int i = 0; i < 16; i++){
        int s = sc*16 + i;
        float w = ws[h*16 + i];
        float4 v4;
        if (s == lp)      v4 = *(const float4*)(g_qkv + b*NE3 + 2*NE + e);
        else if (s == NS) v4 = make_float4(0.f,0.f,0.f,0.f);
        else              v4 = *(const float4*)(vc + (size_t)s*NE + e);
        if (vo) *(float4*)(vo + (size_t)s*NE + e) = v4;
        acc.x = fmaf(w, v4.x, acc.x); acc.y = fmaf(w, v4.y, acc.y);
        acc.z = fmaf(w, v4.z, acc.z); acc.w = fmaf(w, v4.w, acc.w);
    }
    float* p = g_ctx + b*NE + e;
    atomicAdd(p+0, acc.x); atomicAdd(p+1, acc.y);
    atomicAdd(p+2, acc.z); atomicAdd(p+3, acc.w);
}

// ---------------- lm head: warp per 2 vocab rows, coalesced --------------------
__global__ void lm_kernel(const float* __restrict__ wte){
    __shared__ __align__(16) float xs[NB*NE];
    int tid = threadIdx.x;
    for (int i = tid; i < NB*NE; i += 256) xs[i] = g_xln[i];
    __syncthreads();
    int warp = tid >> 5, lane = tid & 31;
    long long t0 = (long long)blockIdx.x*16 + warp*2;
    if (t0 >= NV) return;
    bool has1 = (t0 + 1 < NV);
    const float* r0 = wte + (size_t)t0*NE;
    const float* r1 = has1 ? wte + (size_t)(t0+1)*NE : r0;
    float acc[16];
    #pragma unroll
    for (int i = 0; i < 16; i++) acc[i] = 0.f;
    #pragma unroll
    for (int c = 0; c < 6; c++){
        int e = c*128 + lane*4;
        float4 w0 = *(const float4*)(r0 + e);
        float4 w1 = *(const float4*)(r1 + e);
        #pragma unroll
        for (int b2 = 0; b2 < 8; b2++){
            float4 x4 = *(const float4*)&xs[b2*NE + e];
            acc[b2]   = fmaf(w0.x,x4.x, fmaf(w0.y,x4.y, fmaf(w0.z,x4.z, fmaf(w0.w,x4.w, acc[b2]))));
            acc[8+b2] = fmaf(w1.x,x4.x, fmaf(w1.y,x4.y, fmaf(w1.z,x4.z, fmaf(w1.w,x4.w, acc[8+b2]))));
        }
    }
    #pragma unroll
    for (int i = 0; i < 16; i++){
        float p = acc[i];
        p += __shfl_xor_sync(0xffffffffu, p, 16);
        p += __shfl_xor_sync(0xffffffffu, p, 8);
        p += __shfl_xor_sync(0xffffffffu, p, 4);
        p += __shfl_xor_sync(0xffffffffu, p, 2);
        p += __shfl_xor_sync(0xffffffffu, p, 1);
        acc[i] = p;
    }
    if (lane < 8){
        g_logits[(size_t)lane*NV + t0] = acc[lane];
        if (has1) g_logits[(size_t)lane*NV + t0 + 1] = acc[8 + lane];
    }
}

// ---------------- vocab softmax + argmax ---------------------------------------
__global__ void finish_kernel(float* __restrict__ probs, float* __restrict__ chosen_f,
                              int* __restrict__ chosen_i){
    int b = blockIdx.x, tid = threadIdx.x;
    __shared__ float rv[1024];
    __shared__ int   ri[1024];
    const float* lg = g_logits + (size_t)b*NV;
    float m = -1e30f; int mi = 0;
    for (int t = tid; t < NV; t += 1024){
        float v = lg[t];
        if (v > m){ m = v; mi = t; }
    }
    rv[tid] = m; ri[tid] = mi; __syncthreads();
    for (int o = 512; o; o >>= 1){
        if (tid < o){
            if (rv[tid+o] > rv[tid] || (rv[tid+o] == rv[tid] && ri[tid+o] < ri[tid])){
                rv[tid] = rv[tid+o]; ri[tid] = ri[tid+o];
            }
        }
        __syncthreads();
    }
    float mx = rv[0]; int am = ri[0]; __syncthreads();
    float s = 0.f;
    for (int t = tid; t < NV; t += 1024){
        float ev = expf(lg[t]-mx);
        s += ev;
        if (probs) probs[(size_t)b*NV + t] = ev;
    }
    rv[tid] = s; __syncthreads();
    for (int o = 512; o; o >>= 1){ if (tid < o) rv[tid] += rv[tid+o]; __syncthreads(); }
    float inv = 1.0f/rv[0];
    if (probs)
        for (int t = tid; t < NV; t += 1024)
            probs[(size_t)b*NV + t] *= inv;
    if (tid == 0){
        if (chosen_f) chosen_f[b] = (float)am;
        if (chosen_i) chosen_i[b] = am;
    }
}

// ---------------- launch --------------------------------------------------------
extern "C" void kernel_launch(void* const* d_in, const int* in_sizes, int n_in,
                              void* d_out, int out_size){
    const int*   ids  = (const int*)  d_in[0];
    const int*   mask = (const int*)  d_in[1];
    const float* kv   = (const float*)d_in[2];
    const float* wte  = (const float*)d_in[3];
    const float* wpe  = (const float*)d_in[4];
    const float* ln1w = (const float*)d_in[5];
    const float* ln1b = (const float*)d_in[6];
    const float* caw  = (const float*)d_in[7];
    const float* cab  = (const float*)d_in[8];
    const float* ab   = (const float*)d_in[9];
    const float* cpw  = (const float*)d_in[10];
    const float* cpb  = (const float*)d_in[11];
    const float* ln2w = (const float*)d_in[12];
    const float* ln2b = (const float*)d_in[13];
    const float* fcw  = (const float*)d_in[14];
    const float* fcb  = (const float*)d_in[15];
    const float* prw  = (const float*)d_in[16];
    const float* prb  = (const float*)d_in[17];
    const float* lnfw = (const float*)d_in[18];
    const float* lnfb = (const float*)d_in[19];

    float *st, *xln, *qkvp, *ctxp, *hb;
    cudaGetSymbolAddress((void**)&st,   g_states);
    cudaGetSymbolAddress((void**)&xln,  g_xln);
    cudaGetSymbolAddress((void**)&qkvp, g_qkv);
    cudaGetSymbolAddress((void**)&ctxp, g_ctx);
    cudaGetSymbolAddress((void**)&hb,   g_hbuf);

    long long nkvN  = (long long)NL*2*NB*NS1*NE;                  // 150,994,944
    long long fullN = (long long)NB + (long long)NB*NV + nkvN;    // 151,397,008
    float* outf = (float*)d_out;
    float* chosen_f = nullptr; int* chosen_i = nullptr;
    float* probs = nullptr; float* nkv = nullptr;
    long long osz = (long long)out_size;
    if (osz == fullN){ chosen_f = outf; probs = outf + NB; nkv = outf + NB + (long long)NB*NV; }
    else if (osz == nkvN){ nkv = outf; }
    else if (osz == (long long)NB*NV){ probs = outf; }
    else if (osz == (long long)NB){ chosen_i = (int*)d_out; }
    else if (osz == (long long)NB + (long long)NB*NV){ chosen_f = outf; probs = outf + NB; }
    else {
        chosen_f = outf;
        if (osz >= (long long)NB + (long long)NB*NV) probs = outf + NB;
        if (osz >= fullN) nkv = outf + NB + (long long)NB*NV;
    }

    embed_kernel<<<NB,256>>>(ids, mask, wte, wpe);
    for (int l = 0; l < NL; l++){
        ln_prep_kernel<<<NB,256>>>(st, ln1w + l*NE, ln1b + l*NE, xln, qkvp, NB*NE3, ctxp, NB*NE);
        gemv_kernel<<<dim3(3,48),256>>>(xln, caw + (size_t)l*NE*NE3, cab + (size_t)l*NE3,
                                        qkvp, NE, NE3, 16, 0);
        attn_score_kernel<<<dim3(NB,128),256>>>(kv, ab + (size_t)l*NS1, mask, nkv, l);
        softmax_kernel<<<NB*NH,256>>>();
        attn_v_kernel<<<dim3(NB,64),192>>>(kv, nkv, l);
        gemv_kernel<<<dim3(1,48),256>>>(ctxp, cpw + (size_t)l*NE*NE, cpb + (size_t)l*NE,
                                        st, NE, NE, 16, 0);
        ln_prep_kernel<<<NB,256>>>(st, ln2w + l*NE, ln2b + l*NE, xln, hb, NB*NFF, nullptr, 0);
        gemv_kernel<<<dim3(3,48),256>>>(xln, fcw + (size_t)l*NE*NFF, fcb + (size_t)l*NFF,
                                        hb, NE, NFF, 16, 0);
        gemv_kernel<<<dim3(1,128),256>>>(hb, prw + (size_t)l*NFF*NE, prb + (size_t)l*NE,
                                         st, NFF, NE, 24, 1);
    }
    ln_prep_kernel<<<NB,256>>>(st, lnfw, lnfb, xln, nullptr, 0, nullptr, 0);
    lm_kernel<<<(NV + 15)/16, 256>>>(wte);
    finish_kernel<<<NB,1024>>>(probs, chosen_f, chosen_i);
}